// round 2
// baseline (speedup 1.0000x reference)
#include <cuda_runtime.h>
#include <math.h>

#define NIMG 4
#define NCLS 19
#define HWPIX 589824            // 768*768
#define NTOT (NIMG * HWPIX)
#define IGN 255
#define EDGE_T 0.8f

// ---------------- device-global scratch (no allocations allowed) ----------------
__device__ int    g_seg_bins[NIMG * NCLS];
__device__ int    g_att_bins[NIMG * NCLS];
__device__ int    g_pos;
__device__ int    g_neg;
__device__ float  g_wseg[NIMG * NCLS];
__device__ float  g_watt[NIMG * NCLS];
__device__ float  g_wpos, g_wneg;
// layout: [0..3] num_seg, [4..7] den_seg, [8..11] num_att, [12..15] den_att, [16] bce_sum
__device__ double g_acc[NIMG * 4 + 1];

// ---------------- kernel 0: zero accumulators (graph replays need this) ----------------
__global__ void k_init() {
    int i = threadIdx.x;
    if (i < NIMG * NCLS) { g_seg_bins[i] = 0; g_att_bins[i] = 0; }
    if (i < NIMG * 4 + 1) g_acc[i] = 0.0;
    if (i == 0) { g_pos = 0; g_neg = 0; }
}

// ---------------- kernel 1: per-image class histograms + global pos/neg counts ----------------
// 256 threads x 8 pixels per block; blocks never straddle an image boundary.
__global__ void __launch_bounds__(256) k_hist(const int* __restrict__ seg,
                                              const float* __restrict__ edge,
                                              const int* __restrict__ em) {
    __shared__ int sb[NCLS], ab[NCLS], spn[2];
    int tid = threadIdx.x;
    if (tid < NCLS) { sb[tid] = 0; ab[tid] = 0; }
    if (tid < 2) spn[tid] = 0;
    __syncthreads();

    const int BPI = HWPIX / (256 * 8);     // 288 blocks per image
    int n    = blockIdx.x / BPI;
    int base = n * HWPIX + (blockIdx.x % BPI) * (256 * 8) + tid;

    int lpos = 0, lneg = 0;
#pragma unroll
    for (int k = 0; k < 8; k++) {
        int p = base + k * 256;
        int t = seg[p];
        float e = edge[p];
        if ((unsigned)t < (unsigned)NCLS) {
            atomicAdd(&sb[t], 1);
            if (e > EDGE_T) atomicAdd(&ab[t], 1);
        }
        int m = em[p];
        lpos += (m == 1);
        lneg += (m == 0);
    }
    // warp-reduce pos/neg to cut shared-atomic traffic
    for (int o = 16; o; o >>= 1) {
        lpos += __shfl_down_sync(0xffffffffu, lpos, o);
        lneg += __shfl_down_sync(0xffffffffu, lneg, o);
    }
    if ((tid & 31) == 0) { atomicAdd(&spn[0], lpos); atomicAdd(&spn[1], lneg); }
    __syncthreads();

    if (tid < NCLS) {
        atomicAdd(&g_seg_bins[n * NCLS + tid], sb[tid]);
        atomicAdd(&g_att_bins[n * NCLS + tid], ab[tid]);
    }
    if (tid == 0) atomicAdd(&g_pos, spn[0]);
    if (tid == 1) atomicAdd(&g_neg, spn[1]);
}

// ---------------- kernel 2: turn histograms into CE weights + BCE weights ----------------
__global__ void k_weights() {
    int i = threadIdx.x;
    if (i < NIMG * NCLS) {
        int n = i / NCLS;
        float ssum = 0.f, asum = 0.f;
        for (int c = 0; c < NCLS; c++) {
            ssum += (float)g_seg_bins[n * NCLS + c];
            asum += (float)g_att_bins[n * NCLS + c];
        }
        int sc = g_seg_bins[i], ac = g_att_bins[i];
        // w = (bins!=0)*1.0*(1 - bins/sum) + 1
        g_wseg[i] = sc ? (2.0f - (float)sc / ssum) : 1.0f;
        g_watt[i] = ac ? (2.0f - (float)ac / asum) : 1.0f;
    }
    if (i == 0) {
        float p = (float)g_pos, nn = (float)g_neg;
        float s = p + nn;
        g_wpos = nn / s;   // weight at t==1
        g_wneg = p / s;    // weight at t==0
    }
}

// ---------------- kernel 3: main pass (HBM-bound: reads segin once) ----------------
// 256 threads x 4 pixels (float4/int4 vectorized); 576 blocks per image.
__global__ void __launch_bounds__(256) k_main(const float* __restrict__ segin,
                                              const float* __restrict__ edgein,
                                              const int* __restrict__ segmask,
                                              const int* __restrict__ emask) {
    const int BPI = HWPIX / (256 * 4);     // 576
    int n   = blockIdx.x / BPI;
    int tid = threadIdx.x;

    __shared__ float swseg[NCLS], swatt[NCLS], swe[2];
    if (tid < NCLS) { swseg[tid] = g_wseg[n * NCLS + tid]; swatt[tid] = g_watt[n * NCLS + tid]; }
    if (tid == 0) { swe[0] = g_wpos; swe[1] = g_wneg; }
    __syncthreads();

    int local = (blockIdx.x % BPI) * 1024 + tid * 4;
    int p     = n * HWPIX + local;

    int4   t4 = *(const int4*)(segmask + p);
    float4 e4 = *(const float4*)(edgein + p);
    int4   m4 = *(const int4*)(emask + p);

    int tcls[4] = { min(max(t4.x, 0), NCLS - 1), min(max(t4.y, 0), NCLS - 1),
                    min(max(t4.z, 0), NCLS - 1), min(max(t4.w, 0), NCLS - 1) };
    int tv[4]   = { t4.x, t4.y, t4.z, t4.w };
    float ev[4] = { e4.x, e4.y, e4.z, e4.w };
    int mv[4]   = { m4.x, m4.y, m4.z, m4.w };

    const float* sp = segin + (size_t)n * (size_t)NCLS * (size_t)HWPIX + (size_t)local;

    float s[4]  = {0.f, 0.f, 0.f, 0.f};
    float xt[4] = {0.f, 0.f, 0.f, 0.f};

#pragma unroll
    for (int c = 0; c < NCLS; c++) {
        float4 x = *(const float4*)(sp + (size_t)c * HWPIX);
        s[0] += __expf(x.x);  xt[0] = (c == tcls[0]) ? x.x : xt[0];
        s[1] += __expf(x.y);  xt[1] = (c == tcls[1]) ? x.y : xt[1];
        s[2] += __expf(x.z);  xt[2] = (c == tcls[2]) ? x.z : xt[2];
        s[3] += __expf(x.w);  xt[3] = (c == tcls[3]) ? x.w : xt[3];
    }

    float anum = 0.f, aden = 0.f, bnum = 0.f, bden = 0.f, bce = 0.f;
#pragma unroll
    for (int i = 0; i < 4; i++) {
        float nll = __logf(s[i]) - xt[i];        // = -log_softmax[target]
        bool  v   = (tv[i] != IGN);
        float w   = v ? swseg[tcls[i]] : 0.0f;
        anum += w * nll;  aden += w;
        bool  va  = v && (ev[i] > EDGE_T);
        float wa  = va ? swatt[tcls[i]] : 0.0f;
        bnum += wa * nll; bden += wa;
        float xx  = ev[i];
        float tf  = (float)mv[i];
        float we  = (mv[i] == 1) ? swe[0] : ((mv[i] == 0) ? swe[1] : 0.0f);
        float b   = fmaxf(xx, 0.0f) - xx * tf + log1pf(__expf(-fabsf(xx)));
        bce += we * b;
    }

    // block reduction of 5 floats
    __shared__ float red[8][5];
    float vals[5] = {anum, aden, bnum, bden, bce};
#pragma unroll
    for (int k = 0; k < 5; k++) {
        float v = vals[k];
        for (int o = 16; o; o >>= 1) v += __shfl_down_sync(0xffffffffu, v, o);
        if ((tid & 31) == 0) red[tid >> 5][k] = v;
    }
    __syncthreads();
    if (tid == 0) {
        double a[5] = {0, 0, 0, 0, 0};
#pragma unroll
        for (int w = 0; w < 8; w++)
#pragma unroll
            for (int k = 0; k < 5; k++) a[k] += (double)red[w][k];
        atomicAdd(&g_acc[0 * NIMG + n], a[0]);
        atomicAdd(&g_acc[1 * NIMG + n], a[1]);
        atomicAdd(&g_acc[2 * NIMG + n], a[2]);
        atomicAdd(&g_acc[3 * NIMG + n], a[3]);
        atomicAdd(&g_acc[4 * NIMG],     a[4]);
    }
}

// ---------------- kernel 4: finalize scalar ----------------
__global__ void k_final(float* out) {
    if (threadIdx.x == 0 && blockIdx.x == 0) {
        double segl = 0.0, attl = 0.0;
        for (int i = 0; i < NIMG; i++) {
            segl += g_acc[i]            / g_acc[NIMG + i];
            attl += g_acc[2 * NIMG + i] / g_acc[3 * NIMG + i];
        }
        double edgel = 0.3 * (g_acc[4 * NIMG] / (double)NTOT);
        out[0] = (float)(1.0 * segl + edgel + 0.1 * attl);
    }
}

extern "C" void kernel_launch(void* const* d_in, const int* in_sizes, int n_in,
                              void* d_out, int out_size) {
    const float* segin   = (const float*)d_in[0];
    const float* edgein  = (const float*)d_in[1];
    const int*   segmask = (const int*)d_in[2];
    const int*   emask   = (const int*)d_in[3];

    k_init<<<1, 128>>>();
    k_hist<<<NIMG * (HWPIX / 2048), 256>>>(segmask, edgein, emask);
    k_weights<<<1, 128>>>();
    k_main<<<NIMG * (HWPIX / 1024), 256>>>(segin, edgein, segmask, emask);
    k_final<<<1, 1>>>((float*)d_out);
}